// round 16
// baseline (speedup 1.0000x reference)
#include <cuda_runtime.h>

// gltrivmlp: out[b,g,0:16]=con, out[...,16:32]=clip(con*s),
// out[...,32:48]=clip^2, out[...,48:64]=clip^3, s=rowsum(mat[b,g,:])/16.
// (10-iter reference loop is a 16-lane shift register; fixed point after 3
// iterations; initial val[16:64] is dead.)
//
// FINAL — converged. Samples of this exact source:
//   timed: 25.09 / 25.31 / 25.06 / 27.36 / 26.72 / 27.07 us (median ~25.9)
//   ncu:   26.14 / 25.09 / 24.48 / 26.62 / 24.80 / 25.25 us
// Identical SASS across all samples; spread is DVFS/measurement noise.
// 1184 persistent CTAs (148 SM x 8, all resident at regs<=32), warp-per-row
// round-robin grid-stride, 8x LDG.128 per lane (64 warps/SM x 8 in-flight
// loads = max chip-wide MLP), deferred shfl-reduce, coalesced float2 stores
// with streaming policy. Runs at the device's measured streaming wall
// (~5.8 TB/s; floor ~23.8us for the irreducible 137MB of traffic).
// Falsified alternatives: multi-row/warp (R2), kernel split (R4), blocked
// row mapping (R5), L2 cross-replay retention (R6), cache-policy variants
// (R7), per-warp SW pipelining (R8), 256-bit loads (R11).

#define GS    1024
#define PARAM 64
#define NSM   148
#define BLKS  (NSM * 8)

__global__ __launch_bounds__(256, 8)
void gltrivmlp_kernel(const float* __restrict__ mat,
                      const float* __restrict__ val,
                      float* __restrict__ out,
                      int rows)
{
    const int lane = threadIdx.x & 31;
    const int gw   = blockIdx.x * 8 + (threadIdx.x >> 5);   // global warp id
    const int totw = BLKS * 8;                               // 9472 warps

    const int e0 = lane << 1;        // lane -> output elements {e0, e0+1}
    const int g  = e0 >> 4;          // clip applications: 0..3

    for (int row = gw; row < rows; row += totw) {
        const float4* m = reinterpret_cast<const float4*>(mat + (size_t)row * GS);

        float4 v0 = __ldcs(&m[lane +   0]);
        float4 v1 = __ldcs(&m[lane +  32]);
        float4 v2 = __ldcs(&m[lane +  64]);
        float4 v3 = __ldcs(&m[lane +  96]);
        float4 v4 = __ldcs(&m[lane + 128]);
        float4 v5 = __ldcs(&m[lane + 160]);
        float4 v6 = __ldcs(&m[lane + 192]);
        float4 v7 = __ldcs(&m[lane + 224]);
        float a0 = ((v0.x + v0.y) + (v0.z + v0.w)) + ((v1.x + v1.y) + (v1.z + v1.w));
        float a1 = ((v2.x + v2.y) + (v2.z + v2.w)) + ((v3.x + v3.y) + (v3.z + v3.w));
        float a2 = ((v4.x + v4.y) + (v4.z + v4.w)) + ((v5.x + v5.y) + (v5.z + v5.w));
        float a3 = ((v6.x + v6.y) + (v6.z + v6.w)) + ((v7.x + v7.y) + (v7.z + v7.w));

        float s = (a0 + a1) + (a2 + a3);
        #pragma unroll
        for (int o = 16; o > 0; o >>= 1)
            s += __shfl_xor_sync(0xFFFFFFFFu, s, o);
        const float scale = s * (1.0f / 16.0f);

        const float* con = val + (size_t)row * PARAM;
        float x0 = __ldg(&con[e0 & 15]);
        float x1 = __ldg(&con[(e0 + 1) & 15]);
        #pragma unroll
        for (int i = 0; i < 3; i++) {
            if (i < g) {
                x0 = fminf(fmaxf(x0 * scale, -1.0f), 1.0f);
                x1 = fminf(fmaxf(x1 * scale, -1.0f), 1.0f);
            }
        }
        float2* op = reinterpret_cast<float2*>(out + (size_t)row * PARAM);
        __stcs(&op[lane], make_float2(x0, x1));
    }
}

extern "C" void kernel_launch(void* const* d_in, const int* in_sizes, int n_in,
                              void* d_out, int out_size)
{
    const float* mat = (const float*)d_in[0];   // (32,1024,1024) f32
    const float* val = (const float*)d_in[1];   // (32,1024,64)  f32
    float* out = (float*)d_out;                 // (32,1024,64)  f32

    int rows = in_sizes[0] / GS;                // 32768
    gltrivmlp_kernel<<<BLKS, 256>>>(mat, val, out, rows);
}

// round 17
// speedup vs baseline: 1.0805x; 1.0805x over previous
#include <cuda_runtime.h>

// gltrivmlp: out[b,g,0:16]=con, out[...,16:32]=clip(con*s),
// out[...,32:48]=clip^2, out[...,48:64]=clip^3, s=rowsum(mat[b,g,:])/16.
// (10-iter reference loop is a 16-lane shift register; fixed point after 3
// iterations; initial val[16:64] is dead.)
//
// FINAL — converged. Seven samples of this exact source:
//   timed: 25.09 / 25.31 / 25.06 / 27.36 / 26.72 / 27.07 / 27.07 us
//   ncu:   26.14 / 25.09 / 24.48 / 26.62 / 24.80 / 25.25 / 24.99 us
// Identical SASS across all samples; spread is DVFS/measurement noise.
// 1184 persistent CTAs (148 SM x 8, all resident at regs<=32), warp-per-row
// round-robin grid-stride, 8x LDG.128 per lane (64 warps/SM x 8 in-flight
// loads = max chip-wide MLP), deferred shfl-reduce, coalesced float2 stores
// with streaming policy. Runs at the device's measured streaming wall
// (~5.8 TB/s; floor ~23.8us for the irreducible 137MB of traffic).
// Falsified alternatives: multi-row/warp (R2), kernel split (R4), blocked
// row mapping (R5), L2 cross-replay retention (R6), cache-policy variants
// (R7), per-warp SW pipelining (R8), 256-bit loads (R11).

#define GS    1024
#define PARAM 64
#define NSM   148
#define BLKS  (NSM * 8)

__global__ __launch_bounds__(256, 8)
void gltrivmlp_kernel(const float* __restrict__ mat,
                      const float* __restrict__ val,
                      float* __restrict__ out,
                      int rows)
{
    const int lane = threadIdx.x & 31;
    const int gw   = blockIdx.x * 8 + (threadIdx.x >> 5);   // global warp id
    const int totw = BLKS * 8;                               // 9472 warps

    const int e0 = lane << 1;        // lane -> output elements {e0, e0+1}
    const int g  = e0 >> 4;          // clip applications: 0..3

    for (int row = gw; row < rows; row += totw) {
        const float4* m = reinterpret_cast<const float4*>(mat + (size_t)row * GS);

        float4 v0 = __ldcs(&m[lane +   0]);
        float4 v1 = __ldcs(&m[lane +  32]);
        float4 v2 = __ldcs(&m[lane +  64]);
        float4 v3 = __ldcs(&m[lane +  96]);
        float4 v4 = __ldcs(&m[lane + 128]);
        float4 v5 = __ldcs(&m[lane + 160]);
        float4 v6 = __ldcs(&m[lane + 192]);
        float4 v7 = __ldcs(&m[lane + 224]);
        float a0 = ((v0.x + v0.y) + (v0.z + v0.w)) + ((v1.x + v1.y) + (v1.z + v1.w));
        float a1 = ((v2.x + v2.y) + (v2.z + v2.w)) + ((v3.x + v3.y) + (v3.z + v3.w));
        float a2 = ((v4.x + v4.y) + (v4.z + v4.w)) + ((v5.x + v5.y) + (v5.z + v5.w));
        float a3 = ((v6.x + v6.y) + (v6.z + v6.w)) + ((v7.x + v7.y) + (v7.z + v7.w));

        float s = (a0 + a1) + (a2 + a3);
        #pragma unroll
        for (int o = 16; o > 0; o >>= 1)
            s += __shfl_xor_sync(0xFFFFFFFFu, s, o);
        const float scale = s * (1.0f / 16.0f);

        const float* con = val + (size_t)row * PARAM;
        float x0 = __ldg(&con[e0 & 15]);
        float x1 = __ldg(&con[(e0 + 1) & 15]);
        #pragma unroll
        for (int i = 0; i < 3; i++) {
            if (i < g) {
                x0 = fminf(fmaxf(x0 * scale, -1.0f), 1.0f);
                x1 = fminf(fmaxf(x1 * scale, -1.0f), 1.0f);
            }
        }
        float2* op = reinterpret_cast<float2*>(out + (size_t)row * PARAM);
        __stcs(&op[lane], make_float2(x0, x1));
    }
}

extern "C" void kernel_launch(void* const* d_in, const int* in_sizes, int n_in,
                              void* d_out, int out_size)
{
    const float* mat = (const float*)d_in[0];   // (32,1024,1024) f32
    const float* val = (const float*)d_in[1];   // (32,1024,64)  f32
    float* out = (float*)d_out;                 // (32,1024,64)  f32

    int rows = in_sizes[0] / GS;                // 32768
    gltrivmlp_kernel<<<BLKS, 256>>>(mat, val, out, rows);
}